// round 6
// baseline (speedup 1.0000x reference)
#include <cuda_runtime.h>

// Problem constants
#define HW       16384     // 128*128
#define CIN      512
#define HCIN     256       // channels per K-split half
#define CH       30
#define NPAIR    15        // 30 channels as 15 f32x2 pairs
#define NCLS     17
#define NBATCH   8
#define BN_EPS   1e-5f
#define TPB      256
#define PF       4         // prefetch depth
#define NPAIRS_TOT 65536   // pixel pairs total

typedef unsigned long long u64;

// ---- packed f32x2 helpers ----
__device__ __forceinline__ u64 fma2(u64 a, u64 b, u64 c) {
    u64 d;
    asm("fma.rn.f32x2 %0, %1, %2, %3;" : "=l"(d) : "l"(a), "l"(b), "l"(c));
    return d;
}
__device__ __forceinline__ u64 add2(u64 a, u64 b) {
    u64 d;
    asm("add.rn.f32x2 %0, %1, %2;" : "=l"(d) : "l"(a), "l"(b));
    return d;
}
__device__ __forceinline__ u64 dup2(float v) {
    u64 d;
    asm("mov.b64 %0, {%1, %1};" : "=l"(d) : "f"(v));
    return d;
}
__device__ __forceinline__ u64 pack2(float lo, float hi) {
    u64 d;
    asm("mov.b64 %0, {%1, %2};" : "=l"(d) : "f"(lo), "f"(hi));
    return d;
}
__device__ __forceinline__ float2 unpack2(u64 v) {
    float lo, hi;
    asm("mov.b64 {%0, %1}, %2;" : "=f"(lo), "=f"(hi) : "l"(v));
    return make_float2(lo, hi);
}

// K-split partial sums: [half][pixel-in-pair][ch-pair][pair-idx], f32x2 packed.
// 2*2*15*65536*8B = 31.46 MB static device scratch (sanctioned workaround).
__device__ u64 g_acc[2][2][NPAIR][NPAIRS_TOT];

// ============================ Kernel 1: conv0 partial (K-split) ============================
// grid = 512: bid>>8 selects channel half, bid&255 selects pixel-pair chunk.
// smem: u64 wpack[256*16] = 32KB (BN-folded weights for this half's channels)
#define SMEM1_BYTES (HCIN * 16 * 8)

__global__ __launch_bounds__(TPB, 3) void conv0_partial_kernel(
    const float* __restrict__ x,
    const float* __restrict__ w0,
    const float* __restrict__ b0,
    const float* __restrict__ gamma,
    const float* __restrict__ beta,
    const float* __restrict__ mean,
    const float* __restrict__ var)
{
    extern __shared__ u64 wpack[];           // [256][16] rows of 128B
    __shared__ float scale_s[CH], b0f[CH];

    const int tid  = threadIdx.x;
    const int bid  = blockIdx.x;
    const int half = bid >> 8;
    const int c0   = half << 8;              // first channel of this half

    if (tid < CH) {
        float s = gamma[tid] * rsqrtf(var[tid] + BN_EPS);
        scale_s[tid] = s;
        // bias contributes exactly once: half 0 carries it
        b0f[tid] = (half == 0) ? ((b0[tid] - mean[tid]) * s + beta[tid]) : 0.0f;
    }
    __syncthreads();

    for (int i = tid; i < HCIN * NPAIR; i += TPB) {
        int cl = i / NPAIR;
        int po = i - cl * NPAIR;
        int c  = c0 + cl;
        int o0 = 2 * po, o1 = o0 + 1;
        wpack[(cl << 4) + po] = pack2(w0[o0 * CIN + c] * scale_s[o0],
                                      w0[o1 * CIN + c] * scale_s[o1]);
    }
    __syncthreads();

    const int pp = ((bid & 255) << 8) + tid;   // pixel-pair index 0..65535
    const int gp = pp << 1;
    const int b  = gp >> 14;
    const int hw = gp & (HW - 1);

    const float* xb = x + ((size_t)b * CIN + c0) * HW + hw;

    u64 acc0[NPAIR], acc1[NPAIR];
#pragma unroll
    for (int po = 0; po < NPAIR; po++) {
        u64 bi = pack2(b0f[2 * po], b0f[2 * po + 1]);
        acc0[po] = bi;
        acc1[po] = bi;
    }

    float2 xbuf[PF];
#pragma unroll
    for (int i = 0; i < PF; i++)
        xbuf[i] = __ldcs((const float2*)(xb + (size_t)i * HW));

    for (int cc = 0; cc < HCIN - PF; cc += PF) {
#pragma unroll
        for (int i = 0; i < PF; i++) {
            const int cl = cc + i;
            float2 xv = xbuf[i];
            xbuf[i] = __ldcs((const float2*)(xb + (size_t)(cl + PF) * HW));
            u64 d0 = dup2(xv.x);
            u64 d1 = dup2(xv.y);
            const u64* wr = wpack + (cl << 4);
            const ulonglong2* wv = (const ulonglong2*)wr;
#pragma unroll
            for (int q = 0; q < 7; q++) {
                ulonglong2 w = wv[q];
                acc0[2*q]   = fma2(w.x, d0, acc0[2*q]);
                acc1[2*q]   = fma2(w.x, d1, acc1[2*q]);
                acc0[2*q+1] = fma2(w.y, d0, acc0[2*q+1]);
                acc1[2*q+1] = fma2(w.y, d1, acc1[2*q+1]);
            }
            u64 w14 = wr[14];
            acc0[14] = fma2(w14, d0, acc0[14]);
            acc1[14] = fma2(w14, d1, acc1[14]);
        }
    }
    {
        const int cc = HCIN - PF;
#pragma unroll
        for (int i = 0; i < PF; i++) {
            const int cl = cc + i;
            float2 xv = xbuf[i];
            u64 d0 = dup2(xv.x);
            u64 d1 = dup2(xv.y);
            const u64* wr = wpack + (cl << 4);
            const ulonglong2* wv = (const ulonglong2*)wr;
#pragma unroll
            for (int q = 0; q < 7; q++) {
                ulonglong2 w = wv[q];
                acc0[2*q]   = fma2(w.x, d0, acc0[2*q]);
                acc1[2*q]   = fma2(w.x, d1, acc1[2*q]);
                acc0[2*q+1] = fma2(w.y, d0, acc0[2*q+1]);
                acc1[2*q+1] = fma2(w.y, d1, acc1[2*q+1]);
            }
            u64 w14 = wr[14];
            acc0[14] = fma2(w14, d0, acc0[14]);
            acc1[14] = fma2(w14, d1, acc1[14]);
        }
    }

    // store partials (default .wb stores -> stay L2-resident for kernel 2)
#pragma unroll
    for (int po = 0; po < NPAIR; po++) {
        g_acc[half][0][po][pp] = acc0[po];
        g_acc[half][1][po][pp] = acc1[po];
    }
}

// ============================ Kernel 2: combine + conv1 + argmax + scatter ============================
__global__ __launch_bounds__(TPB, 3) void epilogue_kernel(
    const float* __restrict__ w1,
    const float* __restrict__ b1,
    float* __restrict__ dout,
    int write_logits)
{
    __shared__ float w1s[NCLS * CH];
    __shared__ float b1s[NCLS];

    const int tid = threadIdx.x;
    for (int i = tid; i < NCLS * CH; i += TPB) w1s[i] = w1[i];
    if (tid < NCLS) b1s[tid] = b1[tid];
    __syncthreads();

    const int gp = blockIdx.x * TPB + tid;   // global pixel 0..131071
    const int pp = gp >> 1;
    const int ph = gp & 1;
    const int b  = gp >> 14;
    const int hw = gp & (HW - 1);

    float h[CH];
#pragma unroll
    for (int po = 0; po < NPAIR; po++) {
        u64 s = add2(g_acc[0][ph][po][pp], g_acc[1][ph][po][pp]);
        float2 f = unpack2(s);
        h[2 * po]     = fmaxf(f.x, 0.0f);
        h[2 * po + 1] = fmaxf(f.y, 0.0f);
    }

    float* lg = dout + (size_t)NBATCH * (NCLS * CH) * HW
                     + ((size_t)b * NCLS) * HW + hw;

    float best = -__builtin_huge_valf();
    int cls = 0;
#pragma unroll
    for (int k = 0; k < NCLS; k++) {
        float s = b1s[k];
#pragma unroll
        for (int j = 0; j < CH; j++)
            s = fmaf(w1s[k * CH + j], h[j], s);
        if (s > best) { best = s; cls = k; }    // strict > == first-max (jnp.argmax)
        if (write_logits)
            __stcs(lg + (size_t)k * HW, s);
    }

    float* res = dout + ((size_t)b * (NCLS * CH)) * HW + hw;
#pragma unroll
    for (int k = 0; k < NCLS; k++) {
        const bool m = (k == cls);
#pragma unroll
        for (int j = 0; j < CH; j++)
            __stcs(res + (size_t)(k * CH + j) * HW, m ? h[j] : 0.0f);
    }
}

extern "C" void kernel_launch(void* const* d_in, const int* in_sizes, int n_in,
                              void* d_out, int out_size)
{
    const float* x     = (const float*)d_in[0];
    const float* w0    = (const float*)d_in[1];
    const float* b0    = (const float*)d_in[2];
    const float* gamma = (const float*)d_in[3];
    const float* beta  = (const float*)d_in[4];
    const float* mean  = (const float*)d_in[5];
    const float* var   = (const float*)d_in[6];
    const float* w1    = (const float*)d_in[7];
    const float* b1    = (const float*)d_in[8];

    const long long res_elems   = (long long)NBATCH * NCLS * CH * HW;
    const long long total_elems = res_elems + (long long)NBATCH * NCLS * HW;
    const int write_logits = ((long long)out_size >= total_elems) ? 1 : 0;

    static int configured = 0;
    if (!configured) {
        cudaFuncSetAttribute(conv0_partial_kernel,
                             cudaFuncAttributeMaxDynamicSharedMemorySize, SMEM1_BYTES);
        configured = 1;
    }

    // Kernel 1: 512 blocks (2 halves x 256 pixel-pair chunks)
    conv0_partial_kernel<<<512, TPB, SMEM1_BYTES>>>(
        x, w0, b0, gamma, beta, mean, var);

    // Kernel 2: 512 blocks, 1 pixel per thread
    epilogue_kernel<<<(NBATCH * HW) / TPB, TPB>>>(
        w1, b1, (float*)d_out, write_logits);
}

// round 8
// speedup vs baseline: 1.7440x; 1.7440x over previous
#include <cuda_runtime.h>

// Problem constants
#define HW      16384      // 128*128
#define CIN     512
#define CH      30
#define NPAIR   15         // 30 channels as 15 f32x2 pairs
#define NCLS    17
#define NBATCH  8
#define BN_EPS  1e-5f
#define TPB     256
#define CHB     8          // channels per cp.async block
#define NBLK    (CIN / CHB)   // 64

typedef unsigned long long u64;

// ---- packed f32x2 helpers (Blackwell sm_100a: fma.rn.f32x2) ----
__device__ __forceinline__ u64 fma2(u64 a, u64 b, u64 c) {
    u64 d;
    asm("fma.rn.f32x2 %0, %1, %2, %3;" : "=l"(d) : "l"(a), "l"(b), "l"(c));
    return d;
}
__device__ __forceinline__ u64 dup2(float v) {
    u64 d;
    asm("mov.b64 %0, {%1, %1};" : "=l"(d) : "f"(v));
    return d;
}
__device__ __forceinline__ u64 pack2(float lo, float hi) {
    u64 d;
    asm("mov.b64 %0, {%1, %2};" : "=l"(d) : "f"(lo), "f"(hi));
    return d;
}
__device__ __forceinline__ float2 unpack2(u64 v) {
    float lo, hi;
    asm("mov.b64 {%0, %1}, %2;" : "=f"(lo), "=f"(hi) : "l"(v));
    return make_float2(lo, hi);
}

__device__ __forceinline__ unsigned smem_u32(const void* p) {
    unsigned a;
    asm("{ .reg .u64 t; cvta.to.shared.u64 t, %1; cvt.u32.u64 %0, t; }"
        : "=r"(a) : "l"(p));
    return a;
}
__device__ __forceinline__ void cp8(unsigned dst, const void* src) {
    asm volatile("cp.async.ca.shared.global [%0], [%1], 8;"
                 :: "r"(dst), "l"(src) : "memory");
}
__device__ __forceinline__ void cp_commit() {
    asm volatile("cp.async.commit_group;" ::: "memory");
}
template <int N>
__device__ __forceinline__ void cp_wait() {
    asm volatile("cp.async.wait_group %0;" :: "n"(N) : "memory");
}

// smem layout (dynamic):
//   [0, 65536)         u64 wpack[512*16]       : BN-folded weight pairs, 128B rows
//   [65536, 98304)     float xs[2][CHB][512]   : cp.async x staging ring
//   [98304, 100344)    float w1s[510]
//   [100344, 100412)   float b1s[17]
//   [100412, 100532)   float b0f[30]
#define XS_OFF   65536
#define W1_OFF   98304
#define SMEM_BYTES 100608

__global__ __launch_bounds__(TPB, 2) void fused_segnet_kernel(
    const float* __restrict__ x,
    const float* __restrict__ w0,
    const float* __restrict__ b0,
    const float* __restrict__ gamma,
    const float* __restrict__ beta,
    const float* __restrict__ mean,
    const float* __restrict__ var,
    const float* __restrict__ w1,
    const float* __restrict__ b1,
    float* __restrict__ dout,
    int write_logits)
{
    extern __shared__ unsigned char smem_raw[];
    u64*   wpack = (u64*)smem_raw;
    float* xs    = (float*)(smem_raw + XS_OFF);     // [2][CHB][512]
    float* w1s   = (float*)(smem_raw + W1_OFF);
    float* b1s   = w1s + 510;
    float* b0f   = b1s + NCLS;
    __shared__ float scale_s[CH];

    const int tid = threadIdx.x;

    // ---------- prologue ----------
    if (tid < CH) {
        float s = gamma[tid] * rsqrtf(var[tid] + BN_EPS);
        scale_s[tid] = s;
        b0f[tid] = (b0[tid] - mean[tid]) * s + beta[tid];
    }
    for (int i = tid; i < NCLS * CH; i += TPB) w1s[i] = w1[i];
    if (tid < NCLS) b1s[tid] = b1[tid];
    __syncthreads();

    for (int i = tid; i < CIN * NPAIR; i += TPB) {
        int c  = i / NPAIR;
        int po = i - c * NPAIR;
        int o0 = 2 * po, o1 = o0 + 1;
        wpack[(c << 4) + po] = pack2(w0[o0 * CIN + c] * scale_s[o0],
                                     w0[o1 * CIN + c] * scale_s[o1]);
    }
    __syncthreads();

    // ---------- mainloop: conv0 (512 -> 30) over a pixel pair per thread ----------
    const int pp = blockIdx.x * TPB + tid;     // pixel-pair index
    const int gp = pp << 1;
    const int b  = gp >> 14;
    const int hw = gp & (HW - 1);

    const float* xb = x + ((size_t)b * CIN) * HW + hw;

    // each thread's private smem slot: xs[buf][i][2*tid]
    const unsigned xs_my = smem_u32(xs) + 8u * tid;   // + buf*CHB*512*4 + i*512*4

    u64 acc0[NPAIR], acc1[NPAIR];
#pragma unroll
    for (int po = 0; po < NPAIR; po++) {
        u64 bi = pack2(b0f[2 * po], b0f[2 * po + 1]);
        acc0[po] = bi;
        acc1[po] = bi;
    }

    // prime: stage blocks 0 and 1
#pragma unroll
    for (int i = 0; i < CHB; i++)
        cp8(xs_my + i * 2048u, xb + (size_t)i * HW);
    cp_commit();
#pragma unroll
    for (int i = 0; i < CHB; i++)
        cp8(xs_my + 16384u + i * 2048u, xb + (size_t)(CHB + i) * HW);
    cp_commit();

    for (int bk = 0; bk < NBLK - 1; bk++) {
        cp_wait<1>();                               // block bk resident
        const unsigned xoff = (bk & 1) ? 16384u : 0u;
        const int cbase = bk * CHB;
#pragma unroll
        for (int i = 0; i < CHB; i++) {
            float2 xv;
            asm("ld.shared.v2.f32 {%0, %1}, [%2];"
                : "=f"(xv.x), "=f"(xv.y) : "r"(xs_my + xoff + i * 2048u));
            u64 d0 = dup2(xv.x);
            u64 d1 = dup2(xv.y);
            const u64* wr = wpack + ((cbase + i) << 4);
            const ulonglong2* wv = (const ulonglong2*)wr;
#pragma unroll
            for (int q = 0; q < 7; q++) {
                ulonglong2 w = wv[q];
                acc0[2*q]   = fma2(w.x, d0, acc0[2*q]);
                acc1[2*q]   = fma2(w.x, d1, acc1[2*q]);
                acc0[2*q+1] = fma2(w.y, d0, acc0[2*q+1]);
                acc1[2*q+1] = fma2(w.y, d1, acc1[2*q+1]);
            }
            u64 w14 = wr[14];
            acc0[14] = fma2(w14, d0, acc0[14]);
            acc1[14] = fma2(w14, d1, acc1[14]);
        }
        if (bk + 2 < NBLK) {                        // refill the buffer just consumed
            const size_t cnext = (size_t)(bk + 2) * CHB;
#pragma unroll
            for (int i = 0; i < CHB; i++)
                cp8(xs_my + xoff + i * 2048u, xb + (cnext + i) * HW);
            cp_commit();
        }
    }
    {   // last block (bk = NBLK-1): wait for ALL groups
        cp_wait<0>();
        const int bk = NBLK - 1;
        const unsigned xoff = (bk & 1) ? 16384u : 0u;
        const int cbase = bk * CHB;
#pragma unroll
        for (int i = 0; i < CHB; i++) {
            float2 xv;
            asm("ld.shared.v2.f32 {%0, %1}, [%2];"
                : "=f"(xv.x), "=f"(xv.y) : "r"(xs_my + xoff + i * 2048u));
            u64 d0 = dup2(xv.x);
            u64 d1 = dup2(xv.y);
            const u64* wr = wpack + ((cbase + i) << 4);
            const ulonglong2* wv = (const ulonglong2*)wr;
#pragma unroll
            for (int q = 0; q < 7; q++) {
                ulonglong2 w = wv[q];
                acc0[2*q]   = fma2(w.x, d0, acc0[2*q]);
                acc1[2*q]   = fma2(w.x, d1, acc1[2*q]);
                acc0[2*q+1] = fma2(w.y, d0, acc0[2*q+1]);
                acc1[2*q+1] = fma2(w.y, d1, acc1[2*q+1]);
            }
            u64 w14 = wr[14];
            acc0[14] = fma2(w14, d0, acc0[14]);
            acc1[14] = fma2(w14, d1, acc1[14]);
        }
    }

    // ---------- epilogue: ReLU, conv1 (30 -> 17), argmax, stream logits ----------
    float h0[CH], h1[CH];
#pragma unroll
    for (int po = 0; po < NPAIR; po++) {
        float2 a = unpack2(acc0[po]);
        h0[2 * po]     = fmaxf(a.x, 0.0f);
        h0[2 * po + 1] = fmaxf(a.y, 0.0f);
        float2 bb = unpack2(acc1[po]);
        h1[2 * po]     = fmaxf(bb.x, 0.0f);
        h1[2 * po + 1] = fmaxf(bb.y, 0.0f);
    }

    float* lg = dout + (size_t)NBATCH * (NCLS * CH) * HW
                     + ((size_t)b * NCLS) * HW + hw;

    float best0 = -__builtin_huge_valf(), best1 = -__builtin_huge_valf();
    int cls0 = 0, cls1 = 0;
#pragma unroll
    for (int k = 0; k < NCLS; k++) {
        float s0 = b1s[k], s1 = b1s[k];
#pragma unroll
        for (int j = 0; j < CH; j++) {
            float w = w1s[k * CH + j];
            s0 = fmaf(w, h0[j], s0);
            s1 = fmaf(w, h1[j], s1);
        }
        if (s0 > best0) { best0 = s0; cls0 = k; }   // strict > == first-max (jnp.argmax)
        if (s1 > best1) { best1 = s1; cls1 = k; }
        if (write_logits)
            __stcs((float2*)(lg + (size_t)k * HW), make_float2(s0, s1));
    }

    // ---------- writes: res[b, k*30+j, hw] = (k==cls) * h[j] ----------
    float* res = dout + ((size_t)b * (NCLS * CH)) * HW + hw;
#pragma unroll
    for (int k = 0; k < NCLS; k++) {
        const bool m0 = (k == cls0);
        const bool m1 = (k == cls1);
#pragma unroll
        for (int j = 0; j < CH; j++) {
            float2 v = make_float2(m0 ? h0[j] : 0.0f, m1 ? h1[j] : 0.0f);
            __stcs((float2*)(res + (size_t)(k * CH + j) * HW), v);
        }
    }
}

extern "C" void kernel_launch(void* const* d_in, const int* in_sizes, int n_in,
                              void* d_out, int out_size)
{
    const float* x     = (const float*)d_in[0];
    const float* w0    = (const float*)d_in[1];
    const float* b0    = (const float*)d_in[2];
    const float* gamma = (const float*)d_in[3];
    const float* beta  = (const float*)d_in[4];
    const float* mean  = (const float*)d_in[5];
    const float* var   = (const float*)d_in[6];
    const float* w1    = (const float*)d_in[7];
    const float* b1    = (const float*)d_in[8];

    const long long res_elems   = (long long)NBATCH * NCLS * CH * HW;
    const long long total_elems = res_elems + (long long)NBATCH * NCLS * HW;
    const int write_logits = ((long long)out_size >= total_elems) ? 1 : 0;

    static int configured = 0;
    if (!configured) {
        cudaFuncSetAttribute(fused_segnet_kernel,
                             cudaFuncAttributeMaxDynamicSharedMemorySize, SMEM_BYTES);
        configured = 1;
    }

    const int n_pairs = NBATCH * HW / 2;        // 65536
    const int blocks  = n_pairs / TPB;          // 256
    fused_segnet_kernel<<<blocks, TPB, SMEM_BYTES>>>(
        x, w0, b0, gamma, beta, mean, var, w1, b1, (float*)d_out, write_logits);
}